// round 12
// baseline (speedup 1.0000x reference)
#include <cuda_runtime.h>
#include <cstddef>

// GALA autoencoder: 6 fused layers of out = relu((dyna .* DAD) @ (X @ W + b))
// B=1024, N=255.  fp32 via packed fma.rn.f32x2.
//
// R10 = R5 design with the mask_mul coverage bug fixed (it wrote only cols
// 0..63 of each 256-wide row; now strides across all 256 columns):
//   (a) dyna*dad premultiplied once per distinct DAD into padded [256][256]
//       buffers -> phase-2 loader is 4x LDG.128/thread/tile
//   (b) all tile traffic float4-vectorized
//   (c) double-buffered smem tiles, ONE barrier per k-tile.

#define NN      255
#define NP      256
#define BB      1024
#define TN      64
#define TK      16
#define HS_P    68      // hs row pitch (floats)
#define ASP     260     // k-major tile pitch (floats), rows 16B-aligned
#define NTHREADS 256

// smem floats: hs 256*68=17408, Ast 2*16*260=8320, Ws 2*16*68=2176
#define SMEM_FLOATS (NP*HS_P + 2*TK*ASP + 2*TK*HS_P)
#define SMEM_BYTES  (SMEM_FLOATS * 4)   // 111,616 B -> 2 CTAs/SM

__device__ float g_buf0[(size_t)BB * NN * 400];        // ~418 MB
__device__ float g_buf1[(size_t)BB * NN * 300];        // ~313 MB
__device__ float g_M[4][(size_t)BB * NP * NP];         // 4 x 268 MB padded masks

typedef unsigned long long ull;

__device__ __forceinline__ ull pack_dup(float v) {
    ull r; asm("mov.b64 %0, {%1, %1};" : "=l"(r) : "f"(v)); return r;
}
__device__ __forceinline__ void unpack2(ull v, float& lo, float& hi) {
    asm("mov.b64 {%0, %1}, %2;" : "=f"(lo), "=f"(hi) : "l"(v));
}
__device__ __forceinline__ void ffma2(ull& acc, ull a, ull b) {
    asm("fma.rn.f32x2 %0, %1, %2, %0;" : "+l"(acc) : "l"(a), "l"(b));
}

// ---------------------------------------------------------------------------
// Precompute: Mp[b][i][j] = (i<NN && j<NN) ? dyna[b,i,j]*dad[i,j] : 0
// grid (BB, 16), block 256. Each block covers 16 rows; each thread owns one
// row and strides its float4 quad across ALL 256 columns (fix vs R5).
// ---------------------------------------------------------------------------
__global__ void __launch_bounds__(NTHREADS)
mask_mul(const float* __restrict__ dyna, const float* __restrict__ dad,
         float* __restrict__ Mp)
{
    const int b = blockIdx.x;
    const int i = blockIdx.y * 16 + (threadIdx.x >> 4);
    const float* dyb = dyna + (size_t)b * NN * NN;
    float* mrow = &Mp[((size_t)b * NP + i) * NP];

    for (int j4 = (threadIdx.x & 15) * 4; j4 < NP; j4 += 64) {
        float4 v;
        float* vp = (float*)&v;
#pragma unroll
        for (int q = 0; q < 4; q++) {
            int j = j4 + q;
            vp[q] = (i < NN && j < NN) ? dyb[i * NN + j] * dad[i * NN + j] : 0.f;
        }
        *(float4*)&mrow[j4] = v;
    }
}

// ---------------------------------------------------------------------------
// Fused layer
// ---------------------------------------------------------------------------
__global__ void __launch_bounds__(NTHREADS, 2)
gala_layer(const float* __restrict__ x,      // [B, N, d_in]
           const float* __restrict__ W,      // [d_in, d_out]
           const float* __restrict__ bias,   // [d_out]
           const float* __restrict__ Mp,     // [B, 256, 256] padded mask
           float* __restrict__ out,          // [B, N, d_out]
           int d_in, int d_out)
{
    extern __shared__ float sm[];
    float* hs  = sm;                        // NP*HS_P
    float* Ast = sm + NP * HS_P;            // 2 x TK*ASP  (k-major tiles)
    float* Ws  = Ast + 2 * TK * ASP;        // 2 x TK*HS_P

    const int tid = threadIdx.x;
    const int tr  = tid >> 3;               // 0..31
    const int tc  = tid & 7;                // 0..7
    const int b   = blockIdx.y;
    const int c0  = blockIdx.x * TN;

    // phase-1 X loader: jr row, kq k-quad
    const int jr = tid & 63;
    const int kq = tid >> 6;                // 0..3
    // phase-1 W loader
    const int kr = tid >> 4;                // 0..15
    const int cq = tid & 15;                // 0..15
    // phase-2 M loader
    const int ir  = tid >> 2;               // 0..63
    const int jq  = tid & 3;                // 0..3

    const float* xb  = x  + (size_t)b * NN * d_in;
    const float* Mb  = Mp + (size_t)b * NP * NP;

    ull acc2[8][4];
#pragma unroll
    for (int m = 0; m < 8; m++)
#pragma unroll
        for (int n2 = 0; n2 < 4; n2++) acc2[m][n2] = 0ull;

    // ------------------------------------------------------------------
    // Phase 1: hs[j][c] = sum_k x[b,j,k] * W[k, c0+c]
    // ------------------------------------------------------------------
    const int KT = (d_in + TK - 1) / TK;

    float4 xv[4];
    float4 wv;

    auto loadX = [&](int kt) {
        const int gk = kt * TK + kq * 4;
#pragma unroll
        for (int p = 0; p < 4; p++) {
            const int j = jr + p * 64;
            if (j < NN && gk + 4 <= d_in) {
                xv[p] = *(const float4*)&xb[(size_t)j * d_in + gk];
            } else {
                float* vp = (float*)&xv[p];
#pragma unroll
                for (int q = 0; q < 4; q++)
                    vp[q] = (j < NN && gk + q < d_in) ? xb[(size_t)j * d_in + gk + q] : 0.f;
            }
        }
    };
    auto storeX = [&](int s) {
        float* dst = Ast + s * TK * ASP;
#pragma unroll
        for (int p = 0; p < 4; p++) {
            const int j = jr + p * 64;
            const float* vp = (const float*)&xv[p];
#pragma unroll
            for (int q = 0; q < 4; q++)
                dst[(kq * 4 + q) * ASP + j] = vp[q];
        }
    };
    auto loadW = [&](int kt) {
        const int k = kt * TK + kr;
        const int c = c0 + cq * 4;
        if (k < d_in && c + 4 <= d_out) {
            wv = *(const float4*)&W[(size_t)k * d_out + c];
        } else {
            float* vp = (float*)&wv;
#pragma unroll
            for (int q = 0; q < 4; q++)
                vp[q] = (k < d_in && c + q < d_out) ? W[(size_t)k * d_out + c + q] : 0.f;
        }
    };
    auto storeW = [&](int s) {
        *(float4*)&Ws[s * TK * HS_P + kr * HS_P + cq * 4] = wv;
    };

    auto compute = [&](int s) {
        const float* At = Ast + s * TK * ASP;
        const float* Wt = Ws  + s * TK * HS_P;
#pragma unroll 4
        for (int kk = 0; kk < TK; kk++) {
            const float4 a0 = *(const float4*)&At[kk * ASP + tr * 8];
            const float4 a1 = *(const float4*)&At[kk * ASP + tr * 8 + 4];
            ull xx[8];
            xx[0] = pack_dup(a0.x); xx[1] = pack_dup(a0.y);
            xx[2] = pack_dup(a0.z); xx[3] = pack_dup(a0.w);
            xx[4] = pack_dup(a1.x); xx[5] = pack_dup(a1.y);
            xx[6] = pack_dup(a1.z); xx[7] = pack_dup(a1.w);
            const ulonglong2 w0 = *(const ulonglong2*)&Wt[kk * HS_P + tc * 8];
            const ulonglong2 w1 = *(const ulonglong2*)&Wt[kk * HS_P + tc * 8 + 4];
            const ull wp[4] = {w0.x, w0.y, w1.x, w1.y};
#pragma unroll
            for (int m = 0; m < 8; m++)
#pragma unroll
                for (int n2 = 0; n2 < 4; n2++)
                    ffma2(acc2[m][n2], xx[m], wp[n2]);
        }
    };

    loadX(0); loadW(0);
    storeX(0); storeW(0);
    __syncthreads();

    for (int kt = 0; kt < KT; kt++) {
        const int cur = kt & 1;
        const bool more = (kt + 1 < KT);
        if (more) { loadX(kt + 1); loadW(kt + 1); }
        compute(cur);
        if (more) { storeX(cur ^ 1); storeW(cur ^ 1); }
        __syncthreads();
    }

    // epilogue 1: bias, store hs, reset acc
    {
        float bv[8];
#pragma unroll
        for (int n = 0; n < 8; n++) {
            int c = c0 + tc * 8 + n;
            bv[n] = (c < d_out) ? bias[c] : 0.f;
        }
#pragma unroll
        for (int m = 0; m < 8; m++)
#pragma unroll
            for (int n2 = 0; n2 < 4; n2++) {
                float lo, hi;
                unpack2(acc2[m][n2], lo, hi);
                hs[(tr * 8 + m) * HS_P + tc * 8 + 2 * n2]     = lo + bv[2 * n2];
                hs[(tr * 8 + m) * HS_P + tc * 8 + 2 * n2 + 1] = hi + bv[2 * n2 + 1];
                acc2[m][n2] = 0ull;
            }
    }

    // ------------------------------------------------------------------
    // Phase 2: acc[i][c] = sum_j M[i][j] * hs[j][c]   (M padded, col255=0)
    // ------------------------------------------------------------------
    float4 mv[4];
    auto loadM = [&](int jt) {
        const int j = jt * TK + jq * 4;
#pragma unroll
        for (int p = 0; p < 4; p++)
            mv[p] = *(const float4*)&Mb[(size_t)(ir + p * 64) * NP + j];
    };
    auto storeM = [&](int s) {
        float* dst = Ast + s * TK * ASP;
#pragma unroll
        for (int p = 0; p < 4; p++) {
            const int i = ir + p * 64;
            const float* vp = (const float*)&mv[p];
#pragma unroll
            for (int q = 0; q < 4; q++)
                dst[(jq * 4 + q) * ASP + i] = vp[q];
        }
    };
    auto compute2 = [&](int s, int jt) {
        const float* At = Ast + s * TK * ASP;
        const float* hb = hs + (size_t)jt * TK * HS_P;
#pragma unroll 4
        for (int jj = 0; jj < TK; jj++) {
            const float4 a0 = *(const float4*)&At[jj * ASP + tr * 8];
            const float4 a1 = *(const float4*)&At[jj * ASP + tr * 8 + 4];
            ull aa[8];
            aa[0] = pack_dup(a0.x); aa[1] = pack_dup(a0.y);
            aa[2] = pack_dup(a0.z); aa[3] = pack_dup(a0.w);
            aa[4] = pack_dup(a1.x); aa[5] = pack_dup(a1.y);
            aa[6] = pack_dup(a1.z); aa[7] = pack_dup(a1.w);
            const ulonglong2 h0 = *(const ulonglong2*)&hb[jj * HS_P + tc * 8];
            const ulonglong2 h1 = *(const ulonglong2*)&hb[jj * HS_P + tc * 8 + 4];
            const ull hp[4] = {h0.x, h0.y, h1.x, h1.y};
#pragma unroll
            for (int m = 0; m < 8; m++)
#pragma unroll
                for (int n2 = 0; n2 < 4; n2++)
                    ffma2(acc2[m][n2], aa[m], hp[n2]);
        }
    };

    loadM(0);
    storeM(0);
    __syncthreads();            // publishes hs + M tile 0

    for (int jt = 0; jt < 16; jt++) {
        const int cur = jt & 1;
        const bool more = (jt + 1 < 16);
        if (more) loadM(jt + 1);
        compute2(cur, jt);
        if (more) {
            storeM(cur ^ 1);
            __syncthreads();
        }
    }

    // epilogue 2: ReLU + store (float4 when possible)
#pragma unroll
    for (int m = 0; m < 8; m++) {
        const int i = tr * 8 + m;
        if (i >= NN) continue;
        const size_t base = (size_t)b * NN * d_out + (size_t)i * d_out;
#pragma unroll
        for (int h = 0; h < 2; h++) {
            float v0, v1, v2, v3;
            unpack2(acc2[m][2 * h],     v0, v1);
            unpack2(acc2[m][2 * h + 1], v2, v3);
            const int c = c0 + tc * 8 + 4 * h;
            if (c + 4 <= d_out) {
                float4 o;
                o.x = fmaxf(v0, 0.f); o.y = fmaxf(v1, 0.f);
                o.z = fmaxf(v2, 0.f); o.w = fmaxf(v3, 0.f);
                *(float4*)&out[base + c] = o;
            } else {
                if (c     < d_out) out[base + c]     = fmaxf(v0, 0.f);
                if (c + 1 < d_out) out[base + c + 1] = fmaxf(v1, 0.f);
                if (c + 2 < d_out) out[base + c + 2] = fmaxf(v2, 0.f);
                if (c + 3 < d_out) out[base + c + 3] = fmaxf(v3, 0.f);
            }
        }
    }
}

extern "C" void kernel_launch(void* const* d_in, const int* in_sizes, int n_in,
                              void* d_out, int out_size)
{
    (void)in_sizes; (void)n_in; (void)out_size;

    const float* H    = (const float*)d_in[0];
    const float* dyna = (const float*)d_in[1];
    const float* dads[4] = {
        (const float*)d_in[2],   // t_DADsm
        (const float*)d_in[3],   // s_DADsm
        (const float*)d_in[4],   // s_DADsp
        (const float*)d_in[5],   // t_DADsp
    };
    const float* Wt[6];
    const float* bt[6];
    for (int i = 0; i < 6; i++) {
        Wt[i] = (const float*)d_in[6 + 2 * i];
        bt[i] = (const float*)d_in[7 + 2 * i];
    }

    float *buf0, *buf1, *Mbase;
    cudaGetSymbolAddress((void**)&buf0, g_buf0);
    cudaGetSymbolAddress((void**)&buf1, g_buf1);
    cudaGetSymbolAddress((void**)&Mbase, g_M);
    const size_t Msz = (size_t)BB * NP * NP;

    cudaFuncSetAttribute(gala_layer,
                         cudaFuncAttributeMaxDynamicSharedMemorySize, SMEM_BYTES);

    // precompute the 4 distinct masked adjacencies
    {
        dim3 g(BB, 16), blk(NTHREADS);
        for (int d = 0; d < 4; d++)
            mask_mul<<<g, blk>>>(dyna, dads[d], Mbase + d * Msz);
    }

    const dim3 blk(NTHREADS);
    struct Layer { const float* x; int w; int dd; float* o; int din; int dout; };
    const Layer layers[6] = {
        { H,    0, 0, buf0,           2,   400 },  // t_DADsm
        { buf0, 1, 0, buf1,           400, 300 },  // t_DADsm
        { buf1, 2, 1, buf0,           300, 100 },  // s_DADsm
        { buf0, 3, 2, buf1,           100, 300 },  // s_DADsp
        { buf1, 4, 3, buf0,           300, 400 },  // t_DADsp
        { buf0, 5, 3, (float*)d_out,  400, 2   },  // t_DADsp
    };

    for (int l = 0; l < 6; l++) {
        const Layer& L = layers[l];
        dim3 grd((L.dout + TN - 1) / TN, BB);
        gala_layer<<<grd, blk, SMEM_BYTES>>>(L.x, Wt[L.w], bt[L.w],
                                             Mbase + L.dd * Msz, L.o,
                                             L.din, L.dout);
    }
}

// round 14
// speedup vs baseline: 1.2616x; 1.2616x over previous
#include <cuda_runtime.h>
#include <cuda_bf16.h>
#include <cstdint>
#include <cstddef>

// GALA autoencoder via warp-level tensor-core MMA (mma.sync bf16, sm_80 path —
// compiles under the harness's plain sm_100 PTX target, unlike tcgen05).
//
// out = relu((dyna .* DAD) @ (X @ W + b)) x 6 layers, B=1024, N=255 (pad 256).
// fp32 emulated as bf16 hi/lo split: each GEMM = 3 bf16 MMAs in fp32 accum.
//
// CTA = (batch b, 64-col stripe), 256 thr = 8 warps; warp w owns rows
// 32w..32w+31 x all 64 cols  (2 m16-tiles x 8 n8-tiles, acc 64 f32/thread).
// Phase 1: hs = X@W+b (K chunks of 32 through smem), epilogue writes split
// hs^T into smem. Phase 2: M @ hs with hs^T resident as B operand.

#define NN 255
#define NP 256
#define BB 1024
#define XP 448                  // X gmem K pitch (bf16)
#define NTH 256

// smem byte offsets (all 16B aligned). A rows pitch 80B (conflict-free
// ldmatrix: bank stride 20), hs^T rows pitch 528B (bank stride 4).
#define SM_BIAS 0               // 64 f32
#define SM_AHI  512             // 256 x 80B
#define SM_ALO  (SM_AHI + 20480)
#define SM_BHI  (SM_ALO + 20480)   // 64 x 80B
#define SM_BLO  (SM_BHI + 5120)
#define SM_THI  (SM_BLO + 5120)    // 64 x 528B (hs^T)
#define SM_TLO  (SM_THI + 33792)
#define SMEM_BYTES (SM_TLO + 33792)   // 119,296 B

__device__ __nv_bfloat16 g_Mh[4][(size_t)BB*NP*NP];   // 512 MB
__device__ __nv_bfloat16 g_Ml[4][(size_t)BB*NP*NP];
__device__ __nv_bfloat16 g_Xh[2][(size_t)BB*NP*XP];   // 2 x 224 MB
__device__ __nv_bfloat16 g_Xl[2][(size_t)BB*NP*XP];
__device__ __nv_bfloat16 g_Wh[6][448*448];            // W^T (n-major, K rows)
__device__ __nv_bfloat16 g_Wl[6][448*448];

__device__ __forceinline__ uint32_t smem_u32(const void* p) {
    uint32_t a;
    asm("{ .reg .u64 t; cvta.to.shared.u64 t, %1; cvt.u32.u64 %0, t; }"
        : "=r"(a) : "l"(p));
    return a;
}
__device__ __forceinline__ void ldsm4(uint32_t* r, uint32_t a) {
    asm volatile("ldmatrix.sync.aligned.m8n8.x4.shared.b16 {%0,%1,%2,%3}, [%4];"
                 : "=r"(r[0]), "=r"(r[1]), "=r"(r[2]), "=r"(r[3]) : "r"(a));
}
__device__ __forceinline__ void mma_bf16(float* d, const uint32_t* a,
                                         uint32_t b0, uint32_t b1) {
    asm volatile(
        "mma.sync.aligned.m16n8k16.row.col.f32.bf16.bf16.f32 "
        "{%0,%1,%2,%3}, {%4,%5,%6,%7}, {%8,%9}, {%0,%1,%2,%3};"
        : "+f"(d[0]), "+f"(d[1]), "+f"(d[2]), "+f"(d[3])
        : "r"(a[0]), "r"(a[1]), "r"(a[2]), "r"(a[3]), "r"(b0), "r"(b1));
}
__device__ __forceinline__ void split2(float v, __nv_bfloat16& h, __nv_bfloat16& l) {
    h = __float2bfloat16(v);
    l = __float2bfloat16(v - __bfloat162float(h));
}

// -------------------------------------------------------------- precompute
__global__ void __launch_bounds__(NTH)
split_H_k(const float* __restrict__ H) {
    const int b = blockIdx.x, r = threadIdx.x;
    __nv_bfloat16* ph = &g_Xh[0][((size_t)b * NP + r) * XP];
    __nv_bfloat16* pl = &g_Xl[0][((size_t)b * NP + r) * XP];
    for (int c = 0; c < XP; c++) {
        float v = (r < NN && c < 2) ? H[((size_t)b * NN + r) * 2 + c] : 0.f;
        __nv_bfloat16 h, l; split2(v, h, l);
        ph[c] = h; pl[c] = l;
    }
}

__global__ void __launch_bounds__(NTH)
mask4_k(const float* __restrict__ dyna,
        const float* __restrict__ d0, const float* __restrict__ d1,
        const float* __restrict__ d2, const float* __restrict__ d3) {
    const int b = blockIdx.x;
    const int i = blockIdx.y * 16 + (threadIdx.x >> 4);
    const float* dyb = dyna + (size_t)b * NN * NN;
    const float* dads[4] = {d0, d1, d2, d3};
    const size_t ro = ((size_t)b * NP + i) * NP;
    for (int j0 = (threadIdx.x & 15) * 4; j0 < NP; j0 += 64) {
#pragma unroll
        for (int q = 0; q < 4; q++) {
            const int j = j0 + q;
            const float dy = (i < NN && j < NN) ? dyb[i * NN + j] : 0.f;
#pragma unroll
            for (int d = 0; d < 4; d++) {
                float v = (i < NN && j < NN) ? dy * dads[d][i * NN + j] : 0.f;
                __nv_bfloat16 h, l; split2(v, h, l);
                g_Mh[d][ro + j] = h; g_Ml[d][ro + j] = l;
            }
        }
    }
}

__global__ void __launch_bounds__(128)
wt_split_k(const float* __restrict__ W, int din, int dout, int lw) {
    const int n = blockIdx.x;                 // 0..447
    for (int k = threadIdx.x; k < 448; k += 128) {
        float v = (n < dout && k < din) ? W[(size_t)k * dout + n] : 0.f;
        __nv_bfloat16 h, l; split2(v, h, l);
        g_Wh[lw][(size_t)n * 448 + k] = h;
        g_Wl[lw][(size_t)n * 448 + k] = l;
    }
}

// ------------------------------------------------------------ layer kernel
__global__ void __launch_bounds__(NTH)
gala_mma(const float* __restrict__ bias,
         int xin, int lw, int dd, int dinpad, int dout, int xout,
         float* __restrict__ outf)
{
    extern __shared__ char smem[];
    const uint32_t sb = smem_u32(smem);
    float* sbias = (float*)(smem + SM_BIAS);

    const int tid = threadIdx.x;
    const int w = tid >> 5, lane = tid & 31;
    const int lrow = lane & 15, lcol = lane >> 4;      // ldmatrix addressing
    const int qr = lane >> 2, qc = lane & 3;           // fragment coords
    const int b = blockIdx.y, c0 = blockIdx.x * 64;

    if (tid < 64) { int gc = c0 + tid; sbias[tid] = (gc < dout) ? bias[gc] : 0.f; }

    const __nv_bfloat16* Xh = &g_Xh[xin][(size_t)b * NP * XP];
    const __nv_bfloat16* Xl = &g_Xl[xin][(size_t)b * NP * XP];
    const __nv_bfloat16* Mh = &g_Mh[dd][(size_t)b * NP * NP];
    const __nv_bfloat16* Ml = &g_Ml[dd][(size_t)b * NP * NP];
    const __nv_bfloat16* Wh = &g_Wh[lw][(size_t)c0 * 448];
    const __nv_bfloat16* Wl = &g_Wl[lw][(size_t)c0 * 448];

    float acc[2][8][4];
#pragma unroll
    for (int mt = 0; mt < 2; mt++)
#pragma unroll
        for (int nb = 0; nb < 8; nb++)
#pragma unroll
            for (int f = 0; f < 4; f++) acc[mt][nb][f] = 0.f;

    // ---------------- Phase 1: hs = X @ W  (K chunks of 32) ----------------
    const int KT = dinpad >> 5;
    for (int kc = 0; kc < KT; kc++) {
        const int kOff = kc * 32;
        // A: 256 rows x 32 k (hi+lo): 1024 uint4 each
#pragma unroll
        for (int i = 0; i < 4; i++) {
            const int u = tid + i * 256, r = u >> 2, s = u & 3;
            *(uint4*)(smem + SM_AHI + r * 80 + s * 16) =
                *(const uint4*)(Xh + (size_t)r * XP + kOff + s * 8);
            *(uint4*)(smem + SM_ALO + r * 80 + s * 16) =
                *(const uint4*)(Xl + (size_t)r * XP + kOff + s * 8);
        }
        // B: 64 rows (n) x 32 k
        {
            const int r = tid >> 2, s = tid & 3;
            *(uint4*)(smem + SM_BHI + r * 80 + s * 16) =
                *(const uint4*)(Wh + (size_t)r * 448 + kOff + s * 8);
            *(uint4*)(smem + SM_BLO + r * 80 + s * 16) =
                *(const uint4*)(Wl + (size_t)r * 448 + kOff + s * 8);
        }
        __syncthreads();

#pragma unroll
        for (int s = 0; s < 2; s++) {                  // two k16 steps
            uint32_t ah[2][4], al[2][4];
#pragma unroll
            for (int mt = 0; mt < 2; mt++) {
                const uint32_t ao = (w * 32 + mt * 16 + lrow) * 80 + lcol * 16 + s * 32;
                ldsm4(ah[mt], sb + SM_AHI + ao);
                ldsm4(al[mt], sb + SM_ALO + ao);
            }
#pragma unroll
            for (int nb = 0; nb < 4; nb++) {
                uint32_t bh[4], bl[4];
                const uint32_t bo = (nb * 16 + lrow) * 80 + lcol * 16 + s * 32;
                ldsm4(bh, sb + SM_BHI + bo);
                ldsm4(bl, sb + SM_BLO + bo);
#pragma unroll
                for (int mt = 0; mt < 2; mt++)
#pragma unroll
                    for (int h = 0; h < 2; h++) {
                        float* d = acc[mt][nb * 2 + h];
                        mma_bf16(d, ah[mt], bh[h], bh[2 + h]);
                        mma_bf16(d, ah[mt], bl[h], bl[2 + h]);
                        mma_bf16(d, al[mt], bh[h], bh[2 + h]);
                    }
            }
        }
        __syncthreads();
    }

    // ------- Epilogue 1: +bias, split, transpose hs^T into smem ------------
#pragma unroll
    for (int mt = 0; mt < 2; mt++)
#pragma unroll
        for (int nb = 0; nb < 8; nb++)
#pragma unroll
            for (int f = 0; f < 4; f++) {
                const int j = w * 32 + mt * 16 + qr + ((f >> 1) << 3);
                const int c = nb * 8 + qc * 2 + (f & 1);
                const float v = acc[mt][nb][f] + sbias[c];
                __nv_bfloat16 h, l; split2(v, h, l);
                *(__nv_bfloat16*)(smem + SM_THI + c * 528 + j * 2) = h;
                *(__nv_bfloat16*)(smem + SM_TLO + c * 528 + j * 2) = l;
                acc[mt][nb][f] = 0.f;
            }
    __syncthreads();

    // ---------------- Phase 2: O = M @ hs  (j chunks of 32) ----------------
    for (int kc = 0; kc < 8; kc++) {
        const int jOff = kc * 32;
#pragma unroll
        for (int i = 0; i < 4; i++) {
            const int u = tid + i * 256, r = u >> 2, s = u & 3;
            *(uint4*)(smem + SM_AHI + r * 80 + s * 16) =
                *(const uint4*)(Mh + (size_t)r * NP + jOff + s * 8);
            *(uint4*)(smem + SM_ALO + r * 80 + s * 16) =
                *(const uint4*)(Ml + (size_t)r * NP + jOff + s * 8);
        }
        __syncthreads();

#pragma unroll
        for (int s = 0; s < 2; s++) {
            uint32_t ah[2][4], al[2][4];
#pragma unroll
            for (int mt = 0; mt < 2; mt++) {
                const uint32_t ao = (w * 32 + mt * 16 + lrow) * 80 + lcol * 16 + s * 32;
                ldsm4(ah[mt], sb + SM_AHI + ao);
                ldsm4(al[mt], sb + SM_ALO + ao);
            }
            const uint32_t kb = (jOff + s * 16) * 2;   // byte offset along j
#pragma unroll
            for (int nb = 0; nb < 4; nb++) {
                uint32_t bh[4], bl[4];
                const uint32_t bo = (nb * 16 + lrow) * 528 + lcol * 16 + kb;
                ldsm4(bh, sb + SM_THI + bo);
                ldsm4(bl, sb + SM_TLO + bo);
#pragma unroll
                for (int mt = 0; mt < 2; mt++)
#pragma unroll
                    for (int h = 0; h < 2; h++) {
                        float* d = acc[mt][nb * 2 + h];
                        mma_bf16(d, ah[mt], bh[h], bh[2 + h]);
                        mma_bf16(d, ah[mt], bl[h], bl[2 + h]);
                        mma_bf16(d, al[mt], bh[h], bh[2 + h]);
                    }
            }
        }
        __syncthreads();
    }

    // ------------------ Epilogue 2: ReLU + store ---------------------------
    if (outf != nullptr) {
#pragma unroll
        for (int mt = 0; mt < 2; mt++)
#pragma unroll
            for (int nb = 0; nb < 8; nb++)
#pragma unroll
                for (int f = 0; f < 4; f++) {
                    const int i = w * 32 + mt * 16 + qr + ((f >> 1) << 3);
                    const int c = c0 + nb * 8 + qc * 2 + (f & 1);
                    if (i < NN && c < dout)
                        outf[((size_t)b * NN + i) * dout + c] =
                            fmaxf(acc[mt][nb][f], 0.f);
                }
    } else {
        __nv_bfloat16* Yh = &g_Xh[xout][(size_t)b * NP * XP];
        __nv_bfloat16* Yl = &g_Xl[xout][(size_t)b * NP * XP];
#pragma unroll
        for (int mt = 0; mt < 2; mt++)
#pragma unroll
            for (int nb = 0; nb < 8; nb++)
#pragma unroll
                for (int fp = 0; fp < 2; fp++) {       // fragment row pairs
                    const int i = w * 32 + mt * 16 + qr + fp * 8;
                    const int c = c0 + nb * 8 + qc * 2;
                    const float v0 = (i < NN && c     < dout) ? fmaxf(acc[mt][nb][fp*2],   0.f) : 0.f;
                    const float v1 = (i < NN && c + 1 < dout) ? fmaxf(acc[mt][nb][fp*2+1], 0.f) : 0.f;
                    __nv_bfloat16 h0, l0, h1, l1;
                    split2(v0, h0, l0); split2(v1, h1, l1);
                    __nv_bfloat162 hh; hh.x = h0; hh.y = h1;
                    __nv_bfloat162 ll; ll.x = l0; ll.y = l1;
                    *(__nv_bfloat162*)(Yh + (size_t)i * XP + c) = hh;
                    *(__nv_bfloat162*)(Yl + (size_t)i * XP + c) = ll;
                }
    }
}

// ------------------------------------------------------------------- host
extern "C" void kernel_launch(void* const* d_in, const int* in_sizes, int n_in,
                              void* d_out, int out_size)
{
    (void)in_sizes; (void)n_in; (void)out_size;

    const float* H    = (const float*)d_in[0];
    const float* dyna = (const float*)d_in[1];
    const float* dads[4] = {
        (const float*)d_in[2],   // t_DADsm
        (const float*)d_in[3],   // s_DADsm
        (const float*)d_in[4],   // s_DADsp
        (const float*)d_in[5],   // t_DADsp
    };
    const float* Wt[6];
    const float* bt[6];
    for (int i = 0; i < 6; i++) {
        Wt[i] = (const float*)d_in[6 + 2 * i];
        bt[i] = (const float*)d_in[7 + 2 * i];
    }

    cudaFuncSetAttribute(gala_mma,
                         cudaFuncAttributeMaxDynamicSharedMemorySize, SMEM_BYTES);

    split_H_k<<<BB, NTH>>>(H);
    mask4_k<<<dim3(BB, 16), NTH>>>(dyna, dads[0], dads[1], dads[2], dads[3]);
    struct LT { int din, dout; };
    const LT lt[6] = {{2,400},{400,300},{300,100},{100,300},{300,400},{400,2}};
    for (int l = 0; l < 6; l++)
        wt_split_k<<<448, 128>>>(Wt[l], lt[l].din, lt[l].dout, l);

    // dinpad = pad32(din); X ping-pong 0 -> 1 -> 0 -> ...
    struct L { int xin, lw, dd, dinpad, dout, xout; bool fin; };
    const L ls[6] = {
        {0, 0, 0,  32, 400, 1, false},   // t_DADsm
        {1, 1, 0, 416, 300, 0, false},   // t_DADsm
        {0, 2, 1, 320, 100, 1, false},   // s_DADsm
        {1, 3, 2, 128, 300, 0, false},   // s_DADsp
        {0, 4, 3, 320, 400, 1, false},   // t_DADsp
        {1, 5, 3, 416,   2, 0, true },   // t_DADsp
    };
    for (int l = 0; l < 6; l++) {
        const L& q = ls[l];
        const int stripes = (q.dout + 63) / 64;
        dim3 grd(stripes, BB);
        gala_mma<<<grd, NTH, SMEM_BYTES>>>(bt[q.lw], q.xin, q.lw, q.dd,
                                           q.dinpad, q.dout, q.xout,
                                           q.fin ? (float*)d_out : nullptr);
    }
}

// round 16
// speedup vs baseline: 1.5718x; 1.2459x over previous
#include <cuda_runtime.h>
#include <cuda_bf16.h>
#include <cstdint>
#include <cstddef>

// GALA autoencoder via warp-level tensor-core MMA (mma.sync bf16) with
// cp.async double-buffered staging. sm_100-target safe (no tcgen05).
//
// out = relu((dyna .* DAD) @ (X @ W + b)) x 6 layers, B=1024, N=255 (pad 256).
// fp32 emulated as bf16 hi/lo split: each GEMM tile = 4 bf16 MMAs
// (hh + hl + lh + ll), fp32 accumulation.
//
// CTA = (batch b, 64-col stripe), 512 thr = 16 warps; warp w owns rows
// 16w..16w+15 x all 64 cols (1 m16 x 8 n8 tiles, acc 32 f32/thread).

#define NN 255
#define NP 256
#define BB 1024
#define XP 448                  // X gmem K pitch (bf16)
#define NTH 512

// smem layout. A rows pitch 80B (conflict-free ldmatrix), hs^T pitch 528B.
#define SM_BIAS 0                       // 64 f32 = 256B (+256 pad)
#define A_HI(s) (512 + (s) * 40960)     // 256 x 80B per hi/lo
#define A_LO(s) (A_HI(s) + 20480)
#define B_HI(s) (82432 + (s) * 10240)   // 64 x 80B
#define B_LO(s) (B_HI(s) + 5120)
#define SM_THI  102912                  // 64 x 528B (hs^T hi)
#define SM_TLO  (SM_THI + 33792)
#define SMEM_BYTES (SM_TLO + 33792)     // 170,496 B

__device__ __nv_bfloat16 g_Mh[4][(size_t)BB*NP*NP];   // 512 MB
__device__ __nv_bfloat16 g_Ml[4][(size_t)BB*NP*NP];
__device__ __nv_bfloat16 g_Xh[2][(size_t)BB*NP*XP];
__device__ __nv_bfloat16 g_Xl[2][(size_t)BB*NP*XP];
__device__ __nv_bfloat16 g_Wh[6][448*448];            // W^T (n-major)
__device__ __nv_bfloat16 g_Wl[6][448*448];

__device__ __forceinline__ uint32_t smem_u32(const void* p) {
    uint32_t a;
    asm("{ .reg .u64 t; cvta.to.shared.u64 t, %1; cvt.u32.u64 %0, t; }"
        : "=r"(a) : "l"(p));
    return a;
}
__device__ __forceinline__ void ldsm4(uint32_t* r, uint32_t a) {
    asm volatile("ldmatrix.sync.aligned.m8n8.x4.shared.b16 {%0,%1,%2,%3}, [%4];"
                 : "=r"(r[0]), "=r"(r[1]), "=r"(r[2]), "=r"(r[3]) : "r"(a));
}
__device__ __forceinline__ void mma_bf16(float* d, const uint32_t* a,
                                         uint32_t b0, uint32_t b1) {
    asm volatile(
        "mma.sync.aligned.m16n8k16.row.col.f32.bf16.bf16.f32 "
        "{%0,%1,%2,%3}, {%4,%5,%6,%7}, {%8,%9}, {%0,%1,%2,%3};"
        : "+f"(d[0]), "+f"(d[1]), "+f"(d[2]), "+f"(d[3])
        : "r"(a[0]), "r"(a[1]), "r"(a[2]), "r"(a[3]), "r"(b0), "r"(b1));
}
__device__ __forceinline__ void cpa16(uint32_t dst, const __nv_bfloat16* src) {
    asm volatile("cp.async.cg.shared.global [%0], [%1], 16;"
                 :: "r"(dst), "l"(__cvta_generic_to_global(src)));
}
#define CPA_COMMIT() asm volatile("cp.async.commit_group;" ::: "memory")
#define CPA_WAIT(n)  asm volatile("cp.async.wait_group %0;" :: "n"(n) : "memory")
__device__ __forceinline__ void split2(float v, __nv_bfloat16& h, __nv_bfloat16& l) {
    h = __float2bfloat16(v);
    l = __float2bfloat16(v - __bfloat162float(h));
}

// -------------------------------------------------------------- precompute
__global__ void __launch_bounds__(256)
split_H_k(const float* __restrict__ H) {
    const int b = blockIdx.x, r = threadIdx.x;
    __nv_bfloat16* ph = &g_Xh[0][((size_t)b * NP + r) * XP];
    __nv_bfloat16* pl = &g_Xl[0][((size_t)b * NP + r) * XP];
    for (int c = 0; c < 32; c++) {   // only dinpad=32 is read for layer 0
        float v = (r < NN && c < 2) ? H[((size_t)b * NN + r) * 2 + c] : 0.f;
        __nv_bfloat16 h, l; split2(v, h, l);
        ph[c] = h; pl[c] = l;
    }
}

__global__ void __launch_bounds__(256)
mask4_k(const float* __restrict__ dyna,
        const float* __restrict__ d0, const float* __restrict__ d1,
        const float* __restrict__ d2, const float* __restrict__ d3) {
    const int b = blockIdx.x;
    const int i = blockIdx.y * 16 + (threadIdx.x >> 4);
    const float* dyb = dyna + (size_t)b * NN * NN;
    const float* dads[4] = {d0, d1, d2, d3};
    const size_t ro = ((size_t)b * NP + i) * NP;
    for (int j0 = (threadIdx.x & 15) * 4; j0 < NP; j0 += 64) {
#pragma unroll
        for (int q = 0; q < 4; q++) {
            const int j = j0 + q;
            const float dy = (i < NN && j < NN) ? dyb[i * NN + j] : 0.f;
#pragma unroll
            for (int d = 0; d < 4; d++) {
                float v = (i < NN && j < NN) ? dy * dads[d][i * NN + j] : 0.f;
                __nv_bfloat16 h, l; split2(v, h, l);
                g_Mh[d][ro + j] = h; g_Ml[d][ro + j] = l;
            }
        }
    }
}

__global__ void __launch_bounds__(128)
wt_split_k(const float* __restrict__ W, int din, int dout, int lw) {
    const int n = blockIdx.x;
    for (int k = threadIdx.x; k < 448; k += 128) {
        float v = (n < dout && k < din) ? W[(size_t)k * dout + n] : 0.f;
        __nv_bfloat16 h, l; split2(v, h, l);
        g_Wh[lw][(size_t)n * 448 + k] = h;
        g_Wl[lw][(size_t)n * 448 + k] = l;
    }
}

// ------------------------------------------------------------ layer kernel
__global__ void __launch_bounds__(NTH)
gala_mma(const float* __restrict__ bias,
         int xin, int lw, int dd, int dinpad, int dout, int xout,
         float* __restrict__ outf)
{
    extern __shared__ char smem[];
    const uint32_t sb = smem_u32(smem);
    float* sbias = (float*)(smem + SM_BIAS);

    const int tid = threadIdx.x;
    const int w = tid >> 5, lane = tid & 31;
    const int lrow = lane & 15, lcol = lane >> 4;
    const int qr = lane >> 2, qc = lane & 3;
    const int b = blockIdx.y, c0 = blockIdx.x * 64;

    if (tid < 64) { int gc = c0 + tid; sbias[tid] = (gc < dout) ? bias[gc] : 0.f; }

    const __nv_bfloat16* Xh = &g_Xh[xin][(size_t)b * NP * XP];
    const __nv_bfloat16* Xl = &g_Xl[xin][(size_t)b * NP * XP];
    const __nv_bfloat16* Mh = &g_Mh[dd][(size_t)b * NP * NP];
    const __nv_bfloat16* Ml = &g_Ml[dd][(size_t)b * NP * NP];
    const __nv_bfloat16* Wh = &g_Wh[lw][(size_t)c0 * 448];
    const __nv_bfloat16* Wl = &g_Wl[lw][(size_t)c0 * 448];

    float acc[8][4];
#pragma unroll
    for (int nb = 0; nb < 8; nb++)
#pragma unroll
        for (int f = 0; f < 4; f++) acc[nb][f] = 0.f;

    // loader coords: A (256 rows x 32 k): 1024 uint4 per hi/lo, 2/thread
    const int ar0 = tid >> 2, as0 = tid & 3;       // rows 0..127
    // B (64 rows x 32 k): 256 uint4, tid<256
    const int br = tid >> 2, bs = tid & 3;

    auto issueA = [&](const __nv_bfloat16* Sh, const __nv_bfloat16* Sl,
                      int pitch, int kOff, int buf) {
#pragma unroll
        for (int i = 0; i < 2; i++) {
            const int r = ar0 + i * 128, s = as0;
            const uint32_t o = (uint32_t)(r * 80 + s * 16);
            cpa16(sb + A_HI(buf) + o, Sh + (size_t)r * pitch + kOff + s * 8);
            cpa16(sb + A_LO(buf) + o, Sl + (size_t)r * pitch + kOff + s * 8);
        }
    };
    auto issueB = [&](int kOff, int buf) {
        if (tid < 256) {
            const uint32_t o = (uint32_t)(br * 80 + bs * 16);
            cpa16(sb + B_HI(buf) + o, Wh + (size_t)br * 448 + kOff + bs * 8);
            cpa16(sb + B_LO(buf) + o, Wl + (size_t)br * 448 + kOff + bs * 8);
        }
    };

    // ---------------- Phase 1: hs = X @ W  (K chunks of 32) ----------------
    const int KT = dinpad >> 5;

    issueA(Xh, Xl, XP, 0, 0); issueB(0, 0); CPA_COMMIT();

    for (int kc = 0; kc < KT; kc++) {
        const int cur = kc & 1;
        const bool more = (kc + 1 < KT);
        if (more) {
            issueA(Xh, Xl, XP, (kc + 1) * 32, cur ^ 1);
            issueB((kc + 1) * 32, cur ^ 1);
            CPA_COMMIT();
            CPA_WAIT(1);
        } else {
            CPA_WAIT(0);
        }
        __syncthreads();

#pragma unroll
        for (int s = 0; s < 2; s++) {
            uint32_t ah[4], al[4];
            const uint32_t ao = (uint32_t)((w * 16 + lrow) * 80 + lcol * 16 + s * 32);
            ldsm4(ah, sb + A_HI(cur) + ao);
            ldsm4(al, sb + A_LO(cur) + ao);
#pragma unroll
            for (int nb = 0; nb < 4; nb++) {
                uint32_t bh[4], bl[4];
                const uint32_t bo = (uint32_t)((nb * 16 + lrow) * 80 + lcol * 16 + s * 32);
                ldsm4(bh, sb + B_HI(cur) + bo);
                ldsm4(bl, sb + B_LO(cur) + bo);
#pragma unroll
                for (int h = 0; h < 2; h++) {
                    float* d = acc[nb * 2 + h];
                    mma_bf16(d, ah, bh[h], bh[2 + h]);
                    mma_bf16(d, ah, bl[h], bl[2 + h]);
                    mma_bf16(d, al, bh[h], bh[2 + h]);
                    mma_bf16(d, al, bl[h], bl[2 + h]);
                }
            }
        }
        __syncthreads();
    }

    // ------- Epilogue 1: +bias, split, transpose hs^T into smem ------------
#pragma unroll
    for (int nb = 0; nb < 8; nb++)
#pragma unroll
        for (int f = 0; f < 4; f++) {
            const int j = w * 16 + qr + ((f >> 1) << 3);
            const int c = nb * 8 + qc * 2 + (f & 1);
            const float v = acc[nb][f] + sbias[c];
            __nv_bfloat16 h, l; split2(v, h, l);
            *(__nv_bfloat16*)(smem + SM_THI + c * 528 + j * 2) = h;
            *(__nv_bfloat16*)(smem + SM_TLO + c * 528 + j * 2) = l;
            acc[nb][f] = 0.f;
        }
    __syncthreads();

    // ---------------- Phase 2: O = M @ hs  (j chunks of 32) ----------------
    issueA(Mh, Ml, NP, 0, 0); CPA_COMMIT();

    for (int kc = 0; kc < 8; kc++) {
        const int cur = kc & 1;
        const bool more = (kc + 1 < 8);
        if (more) {
            issueA(Mh, Ml, NP, (kc + 1) * 32, cur ^ 1);
            CPA_COMMIT();
            CPA_WAIT(1);
        } else {
            CPA_WAIT(0);
        }
        __syncthreads();

        const int jOff = kc * 32;
#pragma unroll
        for (int s = 0; s < 2; s++) {
            uint32_t ah[4], al[4];
            const uint32_t ao = (uint32_t)((w * 16 + lrow) * 80 + lcol * 16 + s * 32);
            ldsm4(ah, sb + A_HI(cur) + ao);
            ldsm4(al, sb + A_LO(cur) + ao);
            const uint32_t kb = (uint32_t)((jOff + s * 16) * 2);
#pragma unroll
            for (int nb = 0; nb < 4; nb++) {
                uint32_t bh[4], bl[4];
                const uint32_t bo = (uint32_t)((nb * 16 + lrow) * 528 + lcol * 16 + kb);
                ldsm4(bh, sb + SM_THI + bo);
                ldsm4(bl, sb + SM_TLO + bo);
#pragma unroll
                for (int h = 0; h < 2; h++) {
                    float* d = acc[nb * 2 + h];
                    mma_bf16(d, ah, bh[h], bh[2 + h]);
                    mma_bf16(d, ah, bl[h], bl[2 + h]);
                    mma_bf16(d, al, bh[h], bh[2 + h]);
                    mma_bf16(d, al, bl[h], bl[2 + h]);
                }
            }
        }
        __syncthreads();
    }

    // ------------------ Epilogue 2: ReLU + store ---------------------------
    if (outf != nullptr) {
#pragma unroll
        for (int nb = 0; nb < 8; nb++)
#pragma unroll
            for (int f = 0; f < 4; f++) {
                const int i = w * 16 + qr + ((f >> 1) << 3);
                const int c = c0 + nb * 8 + qc * 2 + (f & 1);
                if (i < NN && c < dout)
                    outf[((size_t)b * NN + i) * dout + c] = fmaxf(acc[nb][f], 0.f);
            }
    } else {
        __nv_bfloat16* Yh = &g_Xh[xout][(size_t)b * NP * XP];
        __nv_bfloat16* Yl = &g_Xl[xout][(size_t)b * NP * XP];
#pragma unroll
        for (int nb = 0; nb < 8; nb++)
#pragma unroll
            for (int fp = 0; fp < 2; fp++) {
                const int i = w * 16 + qr + fp * 8;
                const int c = c0 + nb * 8 + qc * 2;
                const float v0 = (i < NN && c     < dout) ? fmaxf(acc[nb][fp*2],   0.f) : 0.f;
                const float v1 = (i < NN && c + 1 < dout) ? fmaxf(acc[nb][fp*2+1], 0.f) : 0.f;
                __nv_bfloat16 h0, l0, h1, l1;
                split2(v0, h0, l0); split2(v1, h1, l1);
                __nv_bfloat162 hh; hh.x = h0; hh.y = h1;
                __nv_bfloat162 ll; ll.x = l0; ll.y = l1;
                *(__nv_bfloat162*)(Yh + (size_t)i * XP + c) = hh;
                *(__nv_bfloat162*)(Yl + (size_t)i * XP + c) = ll;
            }
    }
}

// ------------------------------------------------------------------- host
extern "C" void kernel_launch(void* const* d_in, const int* in_sizes, int n_in,
                              void* d_out, int out_size)
{
    (void)in_sizes; (void)n_in; (void)out_size;

    const float* H    = (const float*)d_in[0];
    const float* dyna = (const float*)d_in[1];
    const float* dads[4] = {
        (const float*)d_in[2],   // t_DADsm
        (const float*)d_in[3],   // s_DADsm
        (const float*)d_in[4],   // s_DADsp
        (const float*)d_in[5],   // t_DADsp
    };
    const float* Wt[6];
    const float* bt[6];
    for (int i = 0; i < 6; i++) {
        Wt[i] = (const float*)d_in[6 + 2 * i];
        bt[i] = (const float*)d_in[7 + 2 * i];
    }

    cudaFuncSetAttribute(gala_mma,
                         cudaFuncAttributeMaxDynamicSharedMemorySize, SMEM_BYTES);

    split_H_k<<<BB, 256>>>(H);
    mask4_k<<<dim3(BB, 16), 256>>>(dyna, dads[0], dads[1], dads[2], dads[3]);
    struct LT { int din, dout; };
    const LT lt[6] = {{2,400},{400,300},{300,100},{100,300},{300,400},{400,2}};
    for (int l = 0; l < 6; l++)
        wt_split_k<<<448, 128>>>(Wt[l], lt[l].din, lt[l].dout, l);

    // dinpad = pad32(din); X ping-pong 0 -> 1 -> 0 -> ...
    struct L { int xin, lw, dd, dinpad, dout, xout; bool fin; };
    const L ls[6] = {
        {0, 0, 0,  32, 400, 1, false},   // t_DADsm
        {1, 1, 0, 416, 300, 0, false},   // t_DADsm
        {0, 2, 1, 320, 100, 1, false},   // s_DADsm
        {1, 3, 2, 128, 300, 0, false},   // s_DADsp
        {0, 4, 3, 320, 400, 1, false},   // t_DADsp
        {1, 5, 3, 416,   2, 0, true },   // t_DADsp
    };
    for (int l = 0; l < 6; l++) {
        const L& q = ls[l];
        const int stripes = (q.dout + 63) / 64;
        dim3 grd(stripes, BB);
        gala_mma<<<grd, NTH, SMEM_BYTES>>>(bt[q.lw], q.xin, q.lw, q.dd,
                                           q.dinpad, q.dout, q.xout,
                                           q.fin ? (float*)d_out : nullptr);
    }
}